// round 11
// baseline (speedup 1.0000x reference)
#include <cuda_runtime.h>
#include <stdint.h>

typedef unsigned long long ull;

#define DD     1024
#define LLEN   2048
#define KK     32
#define KQ     8            // poles per lane (4-way k-split)
#define NSLOT  4            // 8 poles per lane, packed in pairs
#define CHUNK  256          // time-chunk per chain
#define SREC   8            // recurrence stride
#define STEPS  (CHUNK / SREC)   // 32 steps per chain

// ---- packed f32x2 helpers (sm_100+ PTX; ptxas never emits these from C++) ----
__device__ __forceinline__ ull f2pack(float lo, float hi) {
    ull r;
    asm("mov.b64 %0, {%1, %2};" : "=l"(r) : "r"(__float_as_uint(lo)), "r"(__float_as_uint(hi)));
    return r;
}
__device__ __forceinline__ void f2unpack(ull v, float& lo, float& hi) {
    unsigned a, b;
    asm("mov.b64 {%0, %1}, %2;" : "=r"(a), "=r"(b) : "l"(v));
    lo = __uint_as_float(a);
    hi = __uint_as_float(b);
}
__device__ __forceinline__ ull f2add(ull a, ull b) {
    ull d; asm("add.rn.f32x2 %0, %1, %2;" : "=l"(d) : "l"(a), "l"(b)); return d;
}
__device__ __forceinline__ ull f2mul(ull a, ull b) {
    ull d; asm("mul.rn.f32x2 %0, %1, %2;" : "=l"(d) : "l"(a), "l"(b)); return d;
}
__device__ __forceinline__ ull f2fma(ull a, ull b, ull c) {
    ull d; asm("fma.rn.f32x2 %0, %1, %2, %3;" : "=l"(d) : "l"(a), "l"(b), "l"(c)); return d;
}

__device__ __forceinline__ float reduce4(const ull* x) {
    ull c0 = f2add(x[0], x[1]);
    ull c1 = f2add(x[2], x[3]);
    ull t  = f2add(c0, c1);
    float lo, hi;
    f2unpack(t, lo, hi);
    return lo + hi;
}

// x_k[t] = Re(R_k p_k^t) obeys the stride-8 real recurrence
//   x[t] = A_k x[t-8] + B_k x[t-16],  A_k = 2 Re(p^8),  B_k = -|p^8|^2.
// CTA = 128 threads = one row d. Each warp q runs TWO independent 256-long
// time chains (t0 = q*512 and q*512+256) sharing the same A/B registers —
// doubles the independent advance chains per warp for latency hiding.
// Lane = (kq = lane>>3 pole-quarter, tsub = lane&7 time offset). Merge:
// shfl.xor(8) + shfl.xor(16); lanes kq==0 store. Setup is table-based:
// stage 1 builds rot[k][j] = p^j (j<16) and base[k][c] = R*p^(256c-9) in smem;
// seeds are then two complex-mul real parts per value (no per-thread MUFU).
__global__ void __launch_bounds__(128, 7) modal_kernel(
    const float* __restrict__ rr, const float* __restrict__ th,
    const float* __restrict__ Rre, const float* __restrict__ Rim,
    const float* __restrict__ h0, float* __restrict__ out)
{
    __shared__ float2 sh_rot[KK][16];   // p_k^j
    __shared__ float2 sh_base[KK][8];   // R_k * p_k^(256c - 9)

    const int tid  = threadIdx.x;
    const int lane = tid & 31;
    const int q    = tid >> 5;          // warp = two chains at q*512, q*512+256
    const int d    = blockIdx.x;
    const int tsub = lane & 7;
    const int kq   = lane >> 3;

    const float INV2PI = 0.15915494309189535f;
    const float PI2_HI = 6.2831854820251465f;   // fp32(2*pi)
    const float PI2_LO = -1.7484555e-7f;        // 2*pi - PI2_HI

    // ---- stage 1b: rot table. thread -> (k = tid&31, j = (tid>>5)*4 .. +3) ----
    {
        const int k  = tid & 31;
        const int j0 = (tid >> 5) * 4;
        float rk = __ldg(rr + k * DD + d);
        float tk = __ldg(th + k * DD + d);
        float lr = __logf(rk);
#pragma unroll
        for (int jj = 0; jj < 4; ++jj) {
            int j = j0 + jj;
            float jf = (float)j;
            float rad = __expf(jf * lr);
            float a = jf * tk;                  // <= ~95 rad
            float n = rintf(a * INV2PI);
            a = fmaf(-n, PI2_HI, a);
            a = fmaf(-n, PI2_LO, a);
            float s, c;
            __sincosf(a, &s, &c);
            sh_rot[k][j] = make_float2(rad * c, rad * s);
        }
    }

    // ---- stage 1a: base table. threads 0..31, one k each, 8 chunk-bases ----
    if (tid < KK) {
        const int k = tid;
        const int off = k * DD + d;
        float rk = __ldg(rr + off);
        float tk = __ldg(th + off);
        float ar = __ldg(Rre + off);
        float ai = __ldg(Rim + off);
        float lr = __logf(rk);
#pragma unroll
        for (int c = 0; c < 8; ++c) {
            float ef = 256.0f * (float)c - 9.0f;    // exact in fp32
            float rad = __expf(ef * lr);
            float ph = ef * tk;
            float pe = fmaf(ef, tk, -ph);           // exact low part of product
            float n = rintf(ph * INV2PI);
            float a = fmaf(-n, PI2_HI, ph);
            a = a + pe;
            a = fmaf(-n, PI2_LO, a);
            float s, cc;
            __sincosf(a, &s, &cc);
            sh_base[k][c] = make_float2(rad * (ar * cc - ai * s),
                                        rad * (ar * s + ai * cc));
        }
    }
    __syncthreads();

    // ---- stage 2: seeds for both chains via table products ----
    ull xA1[NSLOT], xA2[NSLOT], xB1[NSLOT], xB2[NSLOT], A[NSLOT], B[NSLOT];
    const int cA = 2 * q, cB = 2 * q + 1;

    float pA1 = 0.f, pA2 = 0.f, pB1 = 0.f, pB2 = 0.f, pCA = 0.f, pCB = 0.f;

#pragma unroll
    for (int kk = 0; kk < KQ; ++kk) {
        const int k = kq * KQ + kk;
        float2 rj  = sh_rot[k][tsub];       // p^tsub
        float2 rj8 = sh_rot[k][tsub + 8];   // p^(tsub+8)
        float2 r8  = sh_rot[k][8];          // p^8
        float2 bA  = sh_base[k][cA];        // R*p^(t0A - 9)
        float2 bB  = sh_base[k][cB];        // R*p^(t0B - 9)

        // x2 at exponent t0 + tsub - 9, x1 at t0 + tsub - 1
        float vA2 = bA.x * rj.x  - bA.y * rj.y;
        float vA1 = bA.x * rj8.x - bA.y * rj8.y;
        float vB2 = bB.x * rj.x  - bB.y * rj.y;
        float vB1 = bB.x * rj8.x - bB.y * rj8.y;
        float cfA = 2.0f * r8.x;
        float cfB = -(r8.x * r8.x + r8.y * r8.y);

        if (kk & 1) {
            xA1[kk >> 1] = f2pack(pA1, vA1);
            xA2[kk >> 1] = f2pack(pA2, vA2);
            xB1[kk >> 1] = f2pack(pB1, vB1);
            xB2[kk >> 1] = f2pack(pB2, vB2);
            A  [kk >> 1] = f2pack(pCA, cfA);
            B  [kk >> 1] = f2pack(pCB, cfB);
        } else {
            pA1 = vA1; pA2 = vA2; pB1 = vB1; pB2 = vB2; pCA = cfA; pCB = cfB;
        }
    }

    float* outA = out + (size_t)d * LLEN + q * 512 + tsub;
    float* outB = outA + CHUNK;
    const bool do_store = (kq == 0);

    // 2-step unrolled main loop over both chains; x1/x2 swap roles each step
#pragma unroll 1
    for (int i = 0; i < STEPS; i += 2) {
        {
            float part = reduce4(xA1);
            float s = part + __shfl_xor_sync(0xffffffffu, part, 8);
            s = s + __shfl_xor_sync(0xffffffffu, s, 16);
            if (do_store) outA[i * SREC] = s;
        }
#pragma unroll
        for (int s2 = 0; s2 < NSLOT; ++s2)
            xA2[s2] = f2fma(A[s2], xA1[s2], f2mul(B[s2], xA2[s2]));
        {
            float part = reduce4(xB1);
            float s = part + __shfl_xor_sync(0xffffffffu, part, 8);
            s = s + __shfl_xor_sync(0xffffffffu, s, 16);
            if (do_store) outB[i * SREC] = s;
        }
#pragma unroll
        for (int s2 = 0; s2 < NSLOT; ++s2)
            xB2[s2] = f2fma(A[s2], xB1[s2], f2mul(B[s2], xB2[s2]));
        {
            float part = reduce4(xA2);
            float s = part + __shfl_xor_sync(0xffffffffu, part, 8);
            s = s + __shfl_xor_sync(0xffffffffu, s, 16);
            if (do_store) outA[(i + 1) * SREC] = s;
        }
#pragma unroll
        for (int s2 = 0; s2 < NSLOT; ++s2)
            xA1[s2] = f2fma(A[s2], xA2[s2], f2mul(B[s2], xA1[s2]));
        {
            float part = reduce4(xB2);
            float s = part + __shfl_xor_sync(0xffffffffu, part, 8);
            s = s + __shfl_xor_sync(0xffffffffu, s, 16);
            if (do_store) outB[(i + 1) * SREC] = s;
        }
#pragma unroll
        for (int s2 = 0; s2 < NSLOT; ++s2)
            xB1[s2] = f2fma(A[s2], xB2[s2], f2mul(B[s2], xB1[s2]));
    }

    // l == 0 carries h_0; same thread (q 0, lane 0) wrote l=0 above
    if (q == 0 && lane == 0) {
        out[(size_t)d * LLEN] = __ldg(h0 + d);
    }
}

extern "C" void kernel_launch(void* const* d_in, const int* in_sizes, int n_in,
                              void* d_out, int out_size) {
    const float* rr  = (const float*)d_in[0];
    const float* th  = (const float*)d_in[1];
    const float* Rre = (const float*)d_in[2];
    const float* Rim = (const float*)d_in[3];
    const float* h0  = (const float*)d_in[4];
    float* out = (float*)d_out;
    modal_kernel<<<DD, 128>>>(rr, th, Rre, Rim, h0, out);
}

// round 12
// speedup vs baseline: 1.0152x; 1.0152x over previous
#include <cuda_runtime.h>
#include <stdint.h>

typedef unsigned long long ull;

#define DD     1024
#define LLEN   2048
#define KK     32
#define KQ     8            // poles per lane (4-way k-split)
#define NSLOT  4            // 8 poles per lane, packed in pairs
#define SEG    512          // time-segment per warp
#define SREC   8            // recurrence stride
#define STEPS  (SEG / SREC)     // 64 steps

// ---- packed f32x2 helpers (sm_100+ PTX; ptxas never emits these from C++) ----
__device__ __forceinline__ ull f2pack(float lo, float hi) {
    ull r;
    asm("mov.b64 %0, {%1, %2};" : "=l"(r) : "r"(__float_as_uint(lo)), "r"(__float_as_uint(hi)));
    return r;
}
__device__ __forceinline__ void f2unpack(ull v, float& lo, float& hi) {
    unsigned a, b;
    asm("mov.b64 {%0, %1}, %2;" : "=r"(a), "=r"(b) : "l"(v));
    lo = __uint_as_float(a);
    hi = __uint_as_float(b);
}
__device__ __forceinline__ ull f2add(ull a, ull b) {
    ull d; asm("add.rn.f32x2 %0, %1, %2;" : "=l"(d) : "l"(a), "l"(b)); return d;
}
__device__ __forceinline__ ull f2mul(ull a, ull b) {
    ull d; asm("mul.rn.f32x2 %0, %1, %2;" : "=l"(d) : "l"(a), "l"(b)); return d;
}
__device__ __forceinline__ ull f2fma(ull a, ull b, ull c) {
    ull d; asm("fma.rn.f32x2 %0, %1, %2, %3;" : "=l"(d) : "l"(a), "l"(b), "l"(c)); return d;
}

__device__ __forceinline__ float reduce4(const ull* x) {
    ull c0 = f2add(x[0], x[1]);
    ull c1 = f2add(x[2], x[3]);
    ull t  = f2add(c0, c1);
    float lo, hi;
    f2unpack(t, lo, hi);
    return lo + hi;
}

// x_k[t] = Re(R_k p_k^t) obeys the stride-8 real recurrence
//   x[t] = A_k x[t-8] + B_k x[t-16],  A_k = 2 Re(p^8),  B_k = -|p^8|^2.
// CTA = 128 threads = one row d; warp seg covers t in [seg*512, (seg+1)*512).
// Lane = (kq = lane>>3 pole-quarter of 8 poles, tsub = lane&7 time offset).
// Merge per step: shfl.xor(8)+add, shfl.xor(16)+add; kq==0 lanes store.
// Setup is table-based: stage 1 builds rot[k][j] = p^j (j<16) and
// base[k][seg] = R*p^(512*seg - 9) in smem; per-thread seeds are then two
// complex-mul real parts per pole (no per-thread transcendentals).
__global__ void __launch_bounds__(128, 8) modal_kernel(
    const float* __restrict__ rr, const float* __restrict__ th,
    const float* __restrict__ Rre, const float* __restrict__ Rim,
    const float* __restrict__ h0, float* __restrict__ out)
{
    __shared__ float2 sh_rot[KK][16];   // p_k^j, j = 0..15
    __shared__ float2 sh_base[KK][4];   // R_k * p_k^(512*seg - 9)

    const int tid  = threadIdx.x;
    const int lane = tid & 31;
    const int seg  = tid >> 5;          // 4 warps = 4 time segments
    const int d    = blockIdx.x;
    const int tsub = lane & 7;
    const int kq   = lane >> 3;

    const float INV2PI = 0.15915494309189535f;
    const float PI2_HI = 6.2831854820251465f;   // fp32(2*pi)
    const float PI2_LO = -1.7484555e-7f;        // 2*pi - PI2_HI

    // ---- stage 1: tables. thread -> (k = tid&31, part = tid>>5) ----
    {
        const int k  = tid & 31;
        const int part = tid >> 5;
        const int off = k * DD + d;
        float rk = __ldg(rr + off);
        float tk = __ldg(th + off);
        float lr = __logf(rk);

        // rot[k][part*4 .. part*4+3] = p^j  (j <= 15, angle <= ~95 rad)
#pragma unroll
        for (int jj = 0; jj < 4; ++jj) {
            int j = part * 4 + jj;
            float jf = (float)j;
            float rad = __expf(jf * lr);
            float a = jf * tk;
            float n = rintf(a * INV2PI);
            a = fmaf(-n, PI2_HI, a);
            a = fmaf(-n, PI2_LO, a);
            float s, c;
            __sincosf(a, &s, &c);
            sh_rot[k][j] = make_float2(rad * c, rad * s);
        }

        // base[k][part] = R * p^(512*part - 9): exact twoProd + 2-term Cody-Waite
        {
            float ar = __ldg(Rre + off);
            float ai = __ldg(Rim + off);
            float ef = 512.0f * (float)part - 9.0f;     // exact in fp32
            float rad = __expf(ef * lr);
            float ph = ef * tk;
            float pe = fmaf(ef, tk, -ph);               // exact low part
            float n = rintf(ph * INV2PI);
            float a = fmaf(-n, PI2_HI, ph);
            a = a + pe;
            a = fmaf(-n, PI2_LO, a);
            float s, c;
            __sincosf(a, &s, &c);
            sh_base[k][part] = make_float2(rad * (ar * c - ai * s),
                                           rad * (ar * s + ai * c));
        }
    }
    __syncthreads();

    // ---- stage 2: seeds via table products; A and B packed in registers ----
    ull x1[NSLOT], x2[NSLOT], A[NSLOT], B[NSLOT];

    float p_x1 = 0.f, p_x2 = 0.f, p_A = 0.f, p_B = 0.f;

#pragma unroll
    for (int kk = 0; kk < KQ; ++kk) {
        const int k = kq * KQ + kk;
        float2 rj  = sh_rot[k][tsub];       // p^tsub
        float2 rj8 = sh_rot[k][tsub + 8];   // p^(tsub+8)
        float2 r8  = sh_rot[k][8];          // p^8
        float2 b   = sh_base[k][seg];       // R*p^(512*seg - 9)

        // x2 at exponent 512*seg + tsub - 9, x1 at +8
        float cx2 = b.x * rj.x  - b.y * rj.y;
        float cx1 = b.x * rj8.x - b.y * rj8.y;
        float cA  = 2.0f * r8.x;
        float cB  = -(r8.x * r8.x + r8.y * r8.y);

        if (kk & 1) {
            x1[kk >> 1] = f2pack(p_x1, cx1);
            x2[kk >> 1] = f2pack(p_x2, cx2);
            A [kk >> 1] = f2pack(p_A,  cA);
            B [kk >> 1] = f2pack(p_B,  cB);
        } else {
            p_x1 = cx1; p_x2 = cx2; p_A = cA; p_B = cB;
        }
    }

    float* outp = out + (size_t)d * LLEN + seg * SEG + tsub;
    const bool do_store = (kq == 0);

    // 4-step unrolled main loop; x1/x2 swap roles every step (no register moves)
#pragma unroll 1
    for (int i = 0; i < STEPS; i += 4) {
        {
            float part = reduce4(x1);
            float s = part + __shfl_xor_sync(0xffffffffu, part, 8);
            s = s + __shfl_xor_sync(0xffffffffu, s, 16);
            if (do_store) outp[i * SREC] = s;
        }
#pragma unroll
        for (int s2 = 0; s2 < NSLOT; ++s2)
            x2[s2] = f2fma(A[s2], x1[s2], f2mul(B[s2], x2[s2]));
        {
            float part = reduce4(x2);
            float s = part + __shfl_xor_sync(0xffffffffu, part, 8);
            s = s + __shfl_xor_sync(0xffffffffu, s, 16);
            if (do_store) outp[(i + 1) * SREC] = s;
        }
#pragma unroll
        for (int s2 = 0; s2 < NSLOT; ++s2)
            x1[s2] = f2fma(A[s2], x2[s2], f2mul(B[s2], x1[s2]));
        {
            float part = reduce4(x1);
            float s = part + __shfl_xor_sync(0xffffffffu, part, 8);
            s = s + __shfl_xor_sync(0xffffffffu, s, 16);
            if (do_store) outp[(i + 2) * SREC] = s;
        }
#pragma unroll
        for (int s2 = 0; s2 < NSLOT; ++s2)
            x2[s2] = f2fma(A[s2], x1[s2], f2mul(B[s2], x2[s2]));
        {
            float part = reduce4(x2);
            float s = part + __shfl_xor_sync(0xffffffffu, part, 8);
            s = s + __shfl_xor_sync(0xffffffffu, s, 16);
            if (do_store) outp[(i + 3) * SREC] = s;
        }
#pragma unroll
        for (int s2 = 0; s2 < NSLOT; ++s2)
            x1[s2] = f2fma(A[s2], x2[s2], f2mul(B[s2], x1[s2]));
    }

    // l == 0 carries h_0; same thread (seg 0, lane 0) wrote l=0 above
    if (seg == 0 && lane == 0) {
        out[(size_t)d * LLEN] = __ldg(h0 + d);
    }
}

extern "C" void kernel_launch(void* const* d_in, const int* in_sizes, int n_in,
                              void* d_out, int out_size) {
    const float* rr  = (const float*)d_in[0];
    const float* th  = (const float*)d_in[1];
    const float* Rre = (const float*)d_in[2];
    const float* Rim = (const float*)d_in[3];
    const float* h0  = (const float*)d_in[4];
    float* out = (float*)d_out;
    modal_kernel<<<DD, 128>>>(rr, th, Rre, Rim, h0, out);
}